// round 10
// baseline (speedup 1.0000x reference)
#include <cuda_runtime.h>
#include <cstdint>

// Problem constants
#define T_ 1024
#define K_ 2
#define E_ 8
#define H_ 2048
#define I_ 1024

#define BM 128
#define KC 32            // K chunk in fp32 elements (= 16 fp16x2 words)
#define HKP 20           // smem row stride in fp16x2 words (16 used + 4 pad)
                         // fragment bank = (20g + t) mod 32 -> all 32 distinct
#define THREADS 256
#define MAX_TILES 24
#define STAGES 3
#define SBW (BM * HKP)                       // words per tile buffer
#define SMEM_BYTES (2 * STAGES * SBW * 4)    // As + Bs = 61440 bytes

// Scratch (device globals — allocation is forbidden)
__device__ int      g_pair_src[T_ * K_];
__device__ int      g_tile_e[MAX_TILES];
__device__ int      g_tile_start[MAX_TILES];
__device__ int      g_tile_cnt[MAX_TILES];
__device__ int      g_num_tiles;
__device__ uint32_t g_inter_h[(size_t)T_ * K_ * I_ / 2];   // 4 MB fp16x2 intermediate

// ---------------------------------------------------------------- helpers
__device__ __forceinline__ uint32_t pack_h2(float lo, float hi) {
    uint32_t r; asm("cvt.rn.f16x2.f32 %0, %1, %2;" : "=r"(r) : "f"(hi), "f"(lo));
    return r;
}

__device__ __forceinline__ void mma_f16(float* c, const uint32_t* a, const uint32_t* b) {
    asm volatile(
        "mma.sync.aligned.m16n8k16.row.col.f32.f16.f16.f32 "
        "{%0,%1,%2,%3}, {%4,%5,%6,%7}, {%8,%9}, {%0,%1,%2,%3};"
        : "+f"(c[0]), "+f"(c[1]), "+f"(c[2]), "+f"(c[3])
        : "r"(a[0]), "r"(a[1]), "r"(a[2]), "r"(a[3]), "r"(b[0]), "r"(b[1]));
}

__device__ __forceinline__ float silu(float x) {
    return x / (1.f + __expf(-x));
}

__device__ __forceinline__ float4 ldg4(const float* p) {
    return __ldg((const float4*)p);
}
__device__ __forceinline__ uint4 ldg4u(const uint32_t* p) {
    return __ldg((const uint4*)p);
}

// ---------------------------------------------------------------- routing
__global__ void route_kernel(const int* __restrict__ sel) {
    __shared__ int cnt[E_], cur[E_];
    int tid = threadIdx.x;
    if (tid < E_) cnt[tid] = 0;
    __syncthreads();
    for (int i = tid; i < T_ * K_; i += blockDim.x) {
        int e = min(max(sel[i], 0), E_ - 1);
        atomicAdd(&cnt[e], 1);
    }
    __syncthreads();
    if (tid == 0) {
        int off = 0, nt = 0;
        for (int e = 0; e < E_; e++) {
            cur[e] = off;
            for (int m = 0; m < cnt[e] && nt < MAX_TILES; m += BM) {
                g_tile_e[nt] = e;
                g_tile_start[nt] = off + m;
                g_tile_cnt[nt] = min(BM, cnt[e] - m);
                nt++;
            }
            off += cnt[e];
        }
        g_num_tiles = nt;
    }
    __syncthreads();
    for (int i = tid; i < T_ * K_; i += blockDim.x) {
        int e = min(max(sel[i], 0), E_ - 1);
        int pos = atomicAdd(&cur[e], 1);
        if (pos < T_ * K_) g_pair_src[pos] = i;   // i = t*K + slot; output row == i
    }
}

// ---------------------------------------------------------------- GEMM1
// inter[pair, n] = silu(x.Wg^T[n]) * (x.Wu^T[n]); CTA: 128 pairs x 64 n-cols.
// C tile 128x128: cols 0..63 = gate(nblk*64..), cols 64..127 = up(same).
__global__ void __launch_bounds__(THREADS, 2)
gemm1_kernel(const float* __restrict__ hs, const float* __restrict__ wgu) {
    const int tile = blockIdx.x;
    if (tile >= g_num_tiles) return;
    const int nblk = blockIdx.y;                 // 0..15  (I/64)
    const int e     = g_tile_e[tile];
    const int start = g_tile_start[tile];
    const int cnt   = g_tile_cnt[tile];
    const int tid = threadIdx.x, wid = tid >> 5, lane = tid & 31;
    const int wm = wid & 3, wn = wid >> 2;
    const int g = lane >> 2, t = lane & 3;

    extern __shared__ uint32_t sm[];
    uint32_t* Asm = sm;                  // [STAGES][BM][HKP] fp16x2 words
    uint32_t* Bsm = sm + STAGES * SBW;
    __shared__ int s_tok[BM];

    if (tid < BM) {
        int v = (tid < cnt) ? g_pair_src[start + tid] : 0;
        s_tok[tid] = v / K_;
    }
    __syncthreads();

    const float* wb = wgu + (size_t)e * (2 * I_) * H_;
    const int srow = tid & 127, shalf = tid >> 7;  // row, half(16 fp32 cols)
    const int wr = (srow < 64) ? (nblk * 64 + srow) : (I_ + nblk * 64 + srow - 64);
    const float* arow = hs + (size_t)s_tok[srow] * H_ + shalf * 16;
    const float* brow = wb + (size_t)wr * H_ + shalf * 16;
    const bool aok = (srow < cnt);
    const int sbase = srow * HKP + shalf * 8;      // word offset in tile buffer

    uint32_t rah[8], rbh[8];   // staged fp16x2 for one chunk (16 cols each side)

#define LOADCVT1(ko)                                                        \
    do {                                                                    \
        _Pragma("unroll")                                                   \
        for (int q = 0; q < 4; q++) {                                       \
            float4 va = aok ? ldg4(arow + (ko) + q * 4)                     \
                            : make_float4(0.f, 0.f, 0.f, 0.f);              \
            rah[2 * q]     = pack_h2(va.x, va.y);                           \
            rah[2 * q + 1] = pack_h2(va.z, va.w);                           \
            float4 vb = ldg4(brow + (ko) + q * 4);                          \
            rbh[2 * q]     = pack_h2(vb.x, vb.y);                           \
            rbh[2 * q + 1] = pack_h2(vb.z, vb.w);                           \
        }                                                                   \
    } while (0)

#define STS_STAGE(s)                                                        \
    do {                                                                    \
        uint32_t* ap = Asm + (s) * SBW + sbase;                             \
        uint32_t* bp = Bsm + (s) * SBW + sbase;                             \
        *(uint4*)ap       = make_uint4(rah[0], rah[1], rah[2], rah[3]);     \
        *(uint4*)(ap + 4) = make_uint4(rah[4], rah[5], rah[6], rah[7]);     \
        *(uint4*)bp       = make_uint4(rbh[0], rbh[1], rbh[2], rbh[3]);     \
        *(uint4*)(bp + 4) = make_uint4(rbh[4], rbh[5], rbh[6], rbh[7]);     \
    } while (0)

    float acc[2][8][4];
#pragma unroll
    for (int mb = 0; mb < 2; mb++)
#pragma unroll
        for (int nb = 0; nb < 8; nb++)
#pragma unroll
            for (int i = 0; i < 4; i++) acc[mb][nb][i] = 0.f;

    const int NK = H_ / KC;
    LOADCVT1(0);
    STS_STAGE(0);
    LOADCVT1(KC);
    __syncthreads();

#pragma unroll 1
    for (int kk = 0; kk < NK; kk++) {
        if (kk + 1 < NK) STS_STAGE((kk + 1) % STAGES);   // regs hold chunk kk+1
        if (kk + 2 < NK) LOADCVT1((kk + 2) * KC);
        const uint32_t* Ab = Asm + (kk % STAGES) * SBW;
        const uint32_t* Bb = Bsm + (kk % STAGES) * SBW;
#pragma unroll
        for (int s2 = 0; s2 < 2; s2++) {                  // two k16 slabs
            const int k0 = s2 * 8;                        // word offset
            uint32_t af[2][4];
#pragma unroll
            for (int mb = 0; mb < 2; mb++) {
                int r = wm * 32 + mb * 16 + g;
                af[mb][0] = Ab[r * HKP + k0 + t];
                af[mb][1] = Ab[(r + 8) * HKP + k0 + t];
                af[mb][2] = Ab[r * HKP + k0 + t + 4];
                af[mb][3] = Ab[(r + 8) * HKP + k0 + t + 4];
            }
            uint32_t bf[8][2];
#pragma unroll
            for (int nb = 0; nb < 8; nb++) {
                int cb = (nb < 4) ? (wn * 32 + nb * 8) : (64 + wn * 32 + (nb - 4) * 8);
                bf[nb][0] = Bb[(cb + g) * HKP + k0 + t];
                bf[nb][1] = Bb[(cb + g) * HKP + k0 + t + 4];
            }
#pragma unroll
            for (int mb = 0; mb < 2; mb++)
#pragma unroll
                for (int nb = 0; nb < 8; nb++)
                    mma_f16(acc[mb][nb], af[mb], bf[nb]);
        }
        __syncthreads();
    }

    // epilogue: silu(gate)*up -> g_inter_h (fp16x2 words; c0/c1 = cols 2t,2t+1)
#pragma unroll
    for (int mb = 0; mb < 2; mb++) {
        int r0 = wm * 32 + mb * 16 + g;
#pragma unroll
        for (int nb = 0; nb < 4; nb++) {
            int colw = (nblk * 64 + wn * 32 + nb * 8) / 2 + t;
            const float* cg = acc[mb][nb];
            const float* cu = acc[mb][nb + 4];
            if (r0 < cnt)
                g_inter_h[(size_t)(start + r0) * (I_ / 2) + colw] =
                    pack_h2(silu(cg[0]) * cu[0], silu(cg[1]) * cu[1]);
            if (r0 + 8 < cnt)
                g_inter_h[(size_t)(start + r0 + 8) * (I_ / 2) + colw] =
                    pack_h2(silu(cg[2]) * cu[2], silu(cg[3]) * cu[3]);
        }
    }
#undef LOADCVT1
#undef STS_STAGE
}

// ---------------------------------------------------------------- GEMM2
// out[src(pair), h] = inter[pair, :] . down[e, h, :]; CTA: 128 pairs x 128 h.
__global__ void __launch_bounds__(THREADS, 2)
gemm2_kernel(const float* __restrict__ dn, float* __restrict__ out) {
    const int tile = blockIdx.x;
    if (tile >= g_num_tiles) return;
    const int nblk = blockIdx.y;                 // 0..15  (H/128)
    const int e     = g_tile_e[tile];
    const int start = g_tile_start[tile];
    const int cnt   = g_tile_cnt[tile];
    const int tid = threadIdx.x, wid = tid >> 5, lane = tid & 31;
    const int wm = wid & 3, wn = wid >> 2;
    const int g = lane >> 2, t = lane & 3;

    extern __shared__ uint32_t sm[];
    uint32_t* Asm = sm;
    uint32_t* Bsm = sm + STAGES * SBW;
    __shared__ int s_src[BM];

    if (tid < BM)
        s_src[tid] = (tid < cnt) ? g_pair_src[start + tid] : 0;
    __syncthreads();

    const float* wb = dn + ((size_t)e * H_ + (size_t)nblk * 128) * I_;
    const int srow = tid & 127, shalf = tid >> 7;
    const uint32_t* arow = g_inter_h + (size_t)(start + ((srow < cnt) ? srow : 0)) * (I_ / 2)
                         + shalf * 8;           // fp16x2 words
    const float* brow = wb + (size_t)srow * I_ + shalf * 16;
    const bool aok = (srow < cnt);
    const int sbase = srow * HKP + shalf * 8;

    uint32_t rah[8], rbh[8];

#define LOADCVT2(kk)                                                        \
    do {                                                                    \
        const int kw = (kk) * (KC / 2);                                     \
        uint4 a0 = aok ? ldg4u(arow + kw) : make_uint4(0, 0, 0, 0);         \
        uint4 a1 = aok ? ldg4u(arow + kw + 4) : make_uint4(0, 0, 0, 0);     \
        rah[0] = a0.x; rah[1] = a0.y; rah[2] = a0.z; rah[3] = a0.w;         \
        rah[4] = a1.x; rah[5] = a1.y; rah[6] = a1.z; rah[7] = a1.w;         \
        _Pragma("unroll")                                                   \
        for (int q = 0; q < 4; q++) {                                       \
            float4 vb = ldg4(brow + (kk) * KC + q * 4);                     \
            rbh[2 * q]     = pack_h2(vb.x, vb.y);                           \
            rbh[2 * q + 1] = pack_h2(vb.z, vb.w);                           \
        }                                                                   \
    } while (0)

#define STS_STAGE(s)                                                        \
    do {                                                                    \
        uint32_t* ap = Asm + (s) * SBW + sbase;                             \
        uint32_t* bp = Bsm + (s) * SBW + sbase;                             \
        *(uint4*)ap       = make_uint4(rah[0], rah[1], rah[2], rah[3]);     \
        *(uint4*)(ap + 4) = make_uint4(rah[4], rah[5], rah[6], rah[7]);     \
        *(uint4*)bp       = make_uint4(rbh[0], rbh[1], rbh[2], rbh[3]);     \
        *(uint4*)(bp + 4) = make_uint4(rbh[4], rbh[5], rbh[6], rbh[7]);     \
    } while (0)

    float acc[2][8][4];
#pragma unroll
    for (int mb = 0; mb < 2; mb++)
#pragma unroll
        for (int nb = 0; nb < 8; nb++)
#pragma unroll
            for (int i = 0; i < 4; i++) acc[mb][nb][i] = 0.f;

    const int NK = I_ / KC;
    LOADCVT2(0);
    STS_STAGE(0);
    LOADCVT2(1);
    __syncthreads();

#pragma unroll 1
    for (int kk = 0; kk < NK; kk++) {
        if (kk + 1 < NK) STS_STAGE((kk + 1) % STAGES);
        if (kk + 2 < NK) LOADCVT2(kk + 2);
        const uint32_t* Ab = Asm + (kk % STAGES) * SBW;
        const uint32_t* Bb = Bsm + (kk % STAGES) * SBW;
#pragma unroll
        for (int s2 = 0; s2 < 2; s2++) {
            const int k0 = s2 * 8;
            uint32_t af[2][4];
#pragma unroll
            for (int mb = 0; mb < 2; mb++) {
                int r = wm * 32 + mb * 16 + g;
                af[mb][0] = Ab[r * HKP + k0 + t];
                af[mb][1] = Ab[(r + 8) * HKP + k0 + t];
                af[mb][2] = Ab[r * HKP + k0 + t + 4];
                af[mb][3] = Ab[(r + 8) * HKP + k0 + t + 4];
            }
            uint32_t bf[8][2];
#pragma unroll
            for (int nb = 0; nb < 8; nb++) {
                int cb = wn * 64 + nb * 8;
                bf[nb][0] = Bb[(cb + g) * HKP + k0 + t];
                bf[nb][1] = Bb[(cb + g) * HKP + k0 + t + 4];
            }
#pragma unroll
            for (int mb = 0; mb < 2; mb++)
#pragma unroll
                for (int nb = 0; nb < 8; nb++)
                    mma_f16(acc[mb][nb], af[mb], bf[nb]);
        }
        __syncthreads();
    }

    // epilogue: scatter rows to out[src] (fp32)
#pragma unroll
    for (int mb = 0; mb < 2; mb++) {
        int r0 = wm * 32 + mb * 16 + g;
        int src0 = s_src[r0 & (BM - 1)];
        int src1 = s_src[(r0 + 8) & (BM - 1)];
#pragma unroll
        for (int nb = 0; nb < 8; nb++) {
            int col = nblk * 128 + wn * 64 + nb * 8 + 2 * t;
            const float* c = acc[mb][nb];
            if (r0 < cnt)
                *(float2*)(out + (size_t)src0 * H_ + col) = make_float2(c[0], c[1]);
            if (r0 + 8 < cnt)
                *(float2*)(out + (size_t)src1 * H_ + col) = make_float2(c[2], c[3]);
        }
    }
#undef LOADCVT2
#undef STS_STAGE
}

// ---------------------------------------------------------------- launch
extern "C" void kernel_launch(void* const* d_in, const int* in_sizes, int n_in,
                              void* d_out, int out_size) {
    // Identify inputs by element count (robust to metadata ordering)
    const float* hs  = nullptr;
    const int*   sel = nullptr;
    const float* wgu = nullptr;
    const float* dn  = nullptr;
    for (int i = 0; i < n_in; i++) {
        long long n = in_sizes[i];
        if (n == (long long)T_ * H_)               hs  = (const float*)d_in[i];
        else if (n == (long long)T_ * K_)          sel = (const int*)d_in[i];
        else if (n == (long long)E_ * 2 * I_ * H_) wgu = (const float*)d_in[i];
        else if (n == (long long)E_ * H_ * I_)     dn  = (const float*)d_in[i];
    }
    float* out = (float*)d_out;
    if (!hs || !sel || !wgu || !dn) return;

    cudaFuncSetAttribute(gemm1_kernel, cudaFuncAttributeMaxDynamicSharedMemorySize, SMEM_BYTES);
    cudaFuncSetAttribute(gemm2_kernel, cudaFuncAttributeMaxDynamicSharedMemorySize, SMEM_BYTES);

    route_kernel<<<1, 256>>>(sel);
    gemm1_kernel<<<dim3(MAX_TILES, I_ / 64), THREADS, SMEM_BYTES>>>(hs, wgu);
    gemm2_kernel<<<dim3(MAX_TILES, H_ / 128), THREADS, SMEM_BYTES>>>(dn, out);
}

// round 11
// speedup vs baseline: 2.3621x; 2.3621x over previous
#include <cuda_runtime.h>
#include <cstdint>

// Problem constants
#define T_ 1024
#define K_ 2
#define E_ 8
#define H_ 2048
#define I_ 1024

#define BM 128
#define KC 32            // K chunk in elements (= 16 fp16x2 words, 64B/row)
#define HKP 20           // smem row stride in fp16x2 words (16 used + 4 pad)
                         // fragment bank = (20g + t) mod 32 -> all 32 distinct
#define THREADS 256
#define MAX_TILES 24
#define STAGES 3
#define SBW (BM * HKP)                       // words per tile buffer (2560)
#define SMEM_BYTES (2 * STAGES * SBW * 4)    // As + Bs = 61440 bytes

// Scratch (device globals — allocation is forbidden)
__device__ int      g_pair_src[T_ * K_];
__device__ int      g_tile_e[MAX_TILES];
__device__ int      g_tile_start[MAX_TILES];
__device__ int      g_tile_cnt[MAX_TILES];
__device__ int      g_num_tiles;
__device__ uint32_t g_hs_h[(size_t)T_ * H_ / 2];             // 4 MB fp16x2
__device__ uint32_t g_wgu_h[(size_t)E_ * 2 * I_ * H_ / 2];   // 67 MB fp16x2
__device__ uint32_t g_dn_h[(size_t)E_ * H_ * I_ / 2];        // 33.5 MB fp16x2
__device__ uint32_t g_inter_h[(size_t)T_ * K_ * I_ / 2];     // 4 MB fp16x2

// ---------------------------------------------------------------- helpers
__device__ __forceinline__ uint32_t pack_h2(float lo, float hi) {
    uint32_t r; asm("cvt.rn.f16x2.f32 %0, %1, %2;" : "=r"(r) : "f"(hi), "f"(lo));
    return r;
}

__device__ __forceinline__ void mma_f16(float* c, const uint32_t* a, const uint32_t* b) {
    asm volatile(
        "mma.sync.aligned.m16n8k16.row.col.f32.f16.f16.f32 "
        "{%0,%1,%2,%3}, {%4,%5,%6,%7}, {%8,%9}, {%0,%1,%2,%3};"
        : "+f"(c[0]), "+f"(c[1]), "+f"(c[2]), "+f"(c[3])
        : "r"(a[0]), "r"(a[1]), "r"(a[2]), "r"(a[3]), "r"(b[0]), "r"(b[1]));
}

__device__ __forceinline__ void cp16(uint32_t dst, const void* src, int srcsize) {
    asm volatile("cp.async.cg.shared.global [%0], [%1], 16, %2;"
                 :: "r"(dst), "l"(src), "r"(srcsize));
}
#define CP_COMMIT()  asm volatile("cp.async.commit_group;")
#define CP_WAIT1()   asm volatile("cp.async.wait_group 1;")

__device__ __forceinline__ float silu(float x) {
    return x / (1.f + __expf(-x));
}

__device__ __forceinline__ float4 ldg4(const float* p) {
    return __ldg((const float4*)p);
}

// ---------------------------------------------------------------- fp32 -> fp16 convert
__global__ void convert_kernel(const float* __restrict__ hs,
                               const float* __restrict__ wgu,
                               const float* __restrict__ dn) {
    const size_t stride = (size_t)gridDim.x * blockDim.x;
    const size_t i0 = (size_t)blockIdx.x * blockDim.x + threadIdx.x;
    // hs: T*H elems -> T*H/4 float4 iters
    for (size_t q = i0; q < (size_t)T_ * H_ / 4; q += stride) {
        float4 v = ldg4(hs + 4 * q);
        *(uint2*)&g_hs_h[2 * q] = make_uint2(pack_h2(v.x, v.y), pack_h2(v.z, v.w));
    }
    for (size_t q = i0; q < (size_t)E_ * 2 * I_ * H_ / 4; q += stride) {
        float4 v = ldg4(wgu + 4 * q);
        *(uint2*)&g_wgu_h[2 * q] = make_uint2(pack_h2(v.x, v.y), pack_h2(v.z, v.w));
    }
    for (size_t q = i0; q < (size_t)E_ * H_ * I_ / 4; q += stride) {
        float4 v = ldg4(dn + 4 * q);
        *(uint2*)&g_dn_h[2 * q] = make_uint2(pack_h2(v.x, v.y), pack_h2(v.z, v.w));
    }
}

// ---------------------------------------------------------------- routing
__global__ void route_kernel(const int* __restrict__ sel) {
    __shared__ int cnt[E_], cur[E_];
    int tid = threadIdx.x;
    if (tid < E_) cnt[tid] = 0;
    __syncthreads();
    for (int i = tid; i < T_ * K_; i += blockDim.x) {
        int e = min(max(sel[i], 0), E_ - 1);
        atomicAdd(&cnt[e], 1);
    }
    __syncthreads();
    if (tid == 0) {
        int off = 0, nt = 0;
        for (int e = 0; e < E_; e++) {
            cur[e] = off;
            for (int m = 0; m < cnt[e] && nt < MAX_TILES; m += BM) {
                g_tile_e[nt] = e;
                g_tile_start[nt] = off + m;
                g_tile_cnt[nt] = min(BM, cnt[e] - m);
                nt++;
            }
            off += cnt[e];
        }
        g_num_tiles = nt;
    }
    __syncthreads();
    for (int i = tid; i < T_ * K_; i += blockDim.x) {
        int e = min(max(sel[i], 0), E_ - 1);
        int pos = atomicAdd(&cur[e], 1);
        if (pos < T_ * K_) g_pair_src[pos] = i;   // i = t*K + slot; output row == i
    }
}

// ---------------------------------------------------------------- GEMM1
// inter[pair, n] = silu(x.Wg^T[n]) * (x.Wu^T[n]); CTA: 128 pairs x 64 n-cols.
// C tile 128x128: cols 0..63 = gate(nblk*64..), cols 64..127 = up(same).
__global__ void __launch_bounds__(THREADS, 2)
gemm1_kernel() {
    const int tile = blockIdx.x;
    if (tile >= g_num_tiles) return;
    const int nblk = blockIdx.y;                 // 0..15  (I/64)
    const int e     = g_tile_e[tile];
    const int start = g_tile_start[tile];
    const int cnt   = g_tile_cnt[tile];
    const int tid = threadIdx.x, wid = tid >> 5, lane = tid & 31;
    const int wm = wid & 3, wn = wid >> 2;
    const int g = lane >> 2, t = lane & 3;

    extern __shared__ uint32_t sm[];
    uint32_t* Asm = sm;                  // [STAGES][BM][HKP] fp16x2 words
    uint32_t* Bsm = sm + STAGES * SBW;
    __shared__ int s_tok[BM];

    if (tid < BM) {
        int v = (tid < cnt) ? g_pair_src[start + tid] : 0;
        s_tok[tid] = v / K_;
    }
    __syncthreads();

    const uint32_t* wbh = g_wgu_h + (size_t)e * (2 * I_) * (H_ / 2);

    // cp.async assignments: per chunk, A tile = 128 rows x 4 quads (16B each)
    // transfer idx ia = tid + j*256, j=0..1 -> row = ia>>2, quad = ia&3
    uint32_t a_dst[2], b_dst[2];
    const uint32_t* a_src[2];
    const uint32_t* b_src[2];
    int a_sz[2];
#pragma unroll
    for (int j = 0; j < 2; j++) {
        int ia = tid + j * THREADS;
        int r = ia >> 2, q = ia & 3;
        a_dst[j] = (uint32_t)__cvta_generic_to_shared(&Asm[r * HKP + q * 4]);
        b_dst[j] = (uint32_t)__cvta_generic_to_shared(&Bsm[r * HKP + q * 4]);
        a_src[j] = g_hs_h + (size_t)s_tok[r] * (H_ / 2) + q * 4;
        int wr = (r < 64) ? (nblk * 64 + r) : (I_ + nblk * 64 + r - 64);
        b_src[j] = wbh + (size_t)wr * (H_ / 2) + q * 4;
        a_sz[j] = (r < cnt) ? 16 : 0;
    }

    float acc[2][8][4];
#pragma unroll
    for (int mb = 0; mb < 2; mb++)
#pragma unroll
        for (int nb = 0; nb < 8; nb++)
#pragma unroll
            for (int i = 0; i < 4; i++) acc[mb][nb][i] = 0.f;

    const int NK = H_ / KC;          // 64 chunks, each 16 words
    // prologue: stages 0,1 in flight
#pragma unroll
    for (int s = 0; s < STAGES - 1; s++) {
        const uint32_t boff = (uint32_t)s * SBW * 4;
#pragma unroll
        for (int j = 0; j < 2; j++) {
            cp16(a_dst[j] + boff, a_src[j] + s * 16, a_sz[j]);
            cp16(b_dst[j] + boff, b_src[j] + s * 16, 16);
        }
        CP_COMMIT();
    }

#pragma unroll 1
    for (int kk = 0; kk < NK; kk++) {
        CP_WAIT1();
        __syncthreads();
        const uint32_t* Ab = Asm + (kk % STAGES) * SBW;
        const uint32_t* Bb = Bsm + (kk % STAGES) * SBW;
#pragma unroll
        for (int s2 = 0; s2 < 2; s2++) {                  // two k16 slabs
            const int k0 = s2 * 8;                        // word offset
            uint32_t af[2][4];
#pragma unroll
            for (int mb = 0; mb < 2; mb++) {
                int r = wm * 32 + mb * 16 + g;
                af[mb][0] = Ab[r * HKP + k0 + t];
                af[mb][1] = Ab[(r + 8) * HKP + k0 + t];
                af[mb][2] = Ab[r * HKP + k0 + t + 4];
                af[mb][3] = Ab[(r + 8) * HKP + k0 + t + 4];
            }
            uint32_t bf[8][2];
#pragma unroll
            for (int nb = 0; nb < 8; nb++) {
                int cb = (nb < 4) ? (wn * 32 + nb * 8) : (64 + wn * 32 + (nb - 4) * 8);
                bf[nb][0] = Bb[(cb + g) * HKP + k0 + t];
                bf[nb][1] = Bb[(cb + g) * HKP + k0 + t + 4];
            }
#pragma unroll
            for (int mb = 0; mb < 2; mb++)
#pragma unroll
                for (int nb = 0; nb < 8; nb++)
                    mma_f16(acc[mb][nb], af[mb], bf[nb]);
        }
        // issue chunk kk+2 into buffer (kk-1)%3 (safe: barrier above ensures
        // all warps finished computing chunk kk-1)
        const int nc = kk + STAGES - 1;
        if (nc < NK) {
            const uint32_t boff = (uint32_t)(nc % STAGES) * SBW * 4;
#pragma unroll
            for (int j = 0; j < 2; j++) {
                cp16(a_dst[j] + boff, a_src[j] + nc * 16, a_sz[j]);
                cp16(b_dst[j] + boff, b_src[j] + nc * 16, 16);
            }
        }
        CP_COMMIT();
    }

    // epilogue: silu(gate)*up -> g_inter_h (fp16x2 words; c0/c1 = cols 2t,2t+1)
#pragma unroll
    for (int mb = 0; mb < 2; mb++) {
        int r0 = wm * 32 + mb * 16 + g;
#pragma unroll
        for (int nb = 0; nb < 4; nb++) {
            int colw = (nblk * 64 + wn * 32 + nb * 8) / 2 + t;
            const float* cg = acc[mb][nb];
            const float* cu = acc[mb][nb + 4];
            if (r0 < cnt)
                g_inter_h[(size_t)(start + r0) * (I_ / 2) + colw] =
                    pack_h2(silu(cg[0]) * cu[0], silu(cg[1]) * cu[1]);
            if (r0 + 8 < cnt)
                g_inter_h[(size_t)(start + r0 + 8) * (I_ / 2) + colw] =
                    pack_h2(silu(cg[2]) * cu[2], silu(cg[3]) * cu[3]);
        }
    }
}

// ---------------------------------------------------------------- GEMM2
// out[src(pair), h] = inter[pair, :] . down[e, h, :]; CTA: 128 pairs x 128 h.
__global__ void __launch_bounds__(THREADS, 2)
gemm2_kernel(float* __restrict__ out) {
    const int tile = blockIdx.x;
    if (tile >= g_num_tiles) return;
    const int nblk = blockIdx.y;                 // 0..15  (H/128)
    const int e     = g_tile_e[tile];
    const int start = g_tile_start[tile];
    const int cnt   = g_tile_cnt[tile];
    const int tid = threadIdx.x, wid = tid >> 5, lane = tid & 31;
    const int wm = wid & 3, wn = wid >> 2;
    const int g = lane >> 2, t = lane & 3;

    extern __shared__ uint32_t sm[];
    uint32_t* Asm = sm;
    uint32_t* Bsm = sm + STAGES * SBW;
    __shared__ int s_src[BM];

    if (tid < BM)
        s_src[tid] = (tid < cnt) ? g_pair_src[start + tid] : 0;
    __syncthreads();

    const uint32_t* wbh = g_dn_h + ((size_t)e * H_ + (size_t)nblk * 128) * (I_ / 2);

    uint32_t a_dst[2], b_dst[2];
    const uint32_t* a_src[2];
    const uint32_t* b_src[2];
    int a_sz[2];
#pragma unroll
    for (int j = 0; j < 2; j++) {
        int ia = tid + j * THREADS;
        int r = ia >> 2, q = ia & 3;
        a_dst[j] = (uint32_t)__cvta_generic_to_shared(&Asm[r * HKP + q * 4]);
        b_dst[j] = (uint32_t)__cvta_generic_to_shared(&Bsm[r * HKP + q * 4]);
        a_src[j] = g_inter_h + (size_t)(start + ((r < cnt) ? r : 0)) * (I_ / 2) + q * 4;
        b_src[j] = wbh + (size_t)r * (I_ / 2) + q * 4;
        a_sz[j] = (r < cnt) ? 16 : 0;
    }

    float acc[2][8][4];
#pragma unroll
    for (int mb = 0; mb < 2; mb++)
#pragma unroll
        for (int nb = 0; nb < 8; nb++)
#pragma unroll
            for (int i = 0; i < 4; i++) acc[mb][nb][i] = 0.f;

    const int NK = I_ / KC;          // 32 chunks
#pragma unroll
    for (int s = 0; s < STAGES - 1; s++) {
        const uint32_t boff = (uint32_t)s * SBW * 4;
#pragma unroll
        for (int j = 0; j < 2; j++) {
            cp16(a_dst[j] + boff, a_src[j] + s * 16, a_sz[j]);
            cp16(b_dst[j] + boff, b_src[j] + s * 16, 16);
        }
        CP_COMMIT();
    }

#pragma unroll 1
    for (int kk = 0; kk < NK; kk++) {
        CP_WAIT1();
        __syncthreads();
        const uint32_t* Ab = Asm + (kk % STAGES) * SBW;
        const uint32_t* Bb = Bsm + (kk % STAGES) * SBW;
#pragma unroll
        for (int s2 = 0; s2 < 2; s2++) {
            const int k0 = s2 * 8;
            uint32_t af[2][4];
#pragma unroll
            for (int mb = 0; mb < 2; mb++) {
                int r = wm * 32 + mb * 16 + g;
                af[mb][0] = Ab[r * HKP + k0 + t];
                af[mb][1] = Ab[(r + 8) * HKP + k0 + t];
                af[mb][2] = Ab[r * HKP + k0 + t + 4];
                af[mb][3] = Ab[(r + 8) * HKP + k0 + t + 4];
            }
            uint32_t bf[8][2];
#pragma unroll
            for (int nb = 0; nb < 8; nb++) {
                int cb = wn * 64 + nb * 8;
                bf[nb][0] = Bb[(cb + g) * HKP + k0 + t];
                bf[nb][1] = Bb[(cb + g) * HKP + k0 + t + 4];
            }
#pragma unroll
            for (int mb = 0; mb < 2; mb++)
#pragma unroll
                for (int nb = 0; nb < 8; nb++)
                    mma_f16(acc[mb][nb], af[mb], bf[nb]);
        }
        const int nc = kk + STAGES - 1;
        if (nc < NK) {
            const uint32_t boff = (uint32_t)(nc % STAGES) * SBW * 4;
#pragma unroll
            for (int j = 0; j < 2; j++) {
                cp16(a_dst[j] + boff, a_src[j] + nc * 16, a_sz[j]);
                cp16(b_dst[j] + boff, b_src[j] + nc * 16, 16);
            }
        }
        CP_COMMIT();
    }

    // epilogue: scatter rows to out[src] (fp32)
#pragma unroll
    for (int mb = 0; mb < 2; mb++) {
        int r0 = wm * 32 + mb * 16 + g;
        int src0 = s_src[r0 & (BM - 1)];
        int src1 = s_src[(r0 + 8) & (BM - 1)];
#pragma unroll
        for (int nb = 0; nb < 8; nb++) {
            int col = nblk * 128 + wn * 64 + nb * 8 + 2 * t;
            const float* c = acc[mb][nb];
            if (r0 < cnt)
                *(float2*)(out + (size_t)src0 * H_ + col) = make_float2(c[0], c[1]);
            if (r0 + 8 < cnt)
                *(float2*)(out + (size_t)src1 * H_ + col) = make_float2(c[2], c[3]);
        }
    }
}

// ---------------------------------------------------------------- launch
extern "C" void kernel_launch(void* const* d_in, const int* in_sizes, int n_in,
                              void* d_out, int out_size) {
    // Identify inputs by element count (robust to metadata ordering)
    const float* hs  = nullptr;
    const int*   sel = nullptr;
    const float* wgu = nullptr;
    const float* dn  = nullptr;
    for (int i = 0; i < n_in; i++) {
        long long n = in_sizes[i];
        if (n == (long long)T_ * H_)               hs  = (const float*)d_in[i];
        else if (n == (long long)T_ * K_)          sel = (const int*)d_in[i];
        else if (n == (long long)E_ * 2 * I_ * H_) wgu = (const float*)d_in[i];
        else if (n == (long long)E_ * H_ * I_)     dn  = (const float*)d_in[i];
    }
    float* out = (float*)d_out;
    if (!hs || !sel || !wgu || !dn) return;

    cudaFuncSetAttribute(gemm1_kernel, cudaFuncAttributeMaxDynamicSharedMemorySize, SMEM_BYTES);
    cudaFuncSetAttribute(gemm2_kernel, cudaFuncAttributeMaxDynamicSharedMemorySize, SMEM_BYTES);

    convert_kernel<<<2048, 256>>>(hs, wgu, dn);
    route_kernel<<<1, 256>>>(sel);
    gemm1_kernel<<<dim3(MAX_TILES, I_ / 64), THREADS, SMEM_BYTES>>>();
    gemm2_kernel<<<dim3(MAX_TILES, H_ / 128), THREADS, SMEM_BYTES>>>(out);
}

// round 12
// speedup vs baseline: 2.8420x; 1.2031x over previous
#include <cuda_runtime.h>
#include <cstdint>

// Problem constants
#define T_ 1024
#define K_ 2
#define E_ 8
#define H_ 2048
#define I_ 1024

#define BM 128
#define KC 64            // K chunk in elements (= 32 fp16x2 words, 128B/row)
#define HKP 36           // smem row stride in fp16x2 words (32 used + 4 pad)
                         // bank = (4r + c) mod 32 -> conflict-free frags + ldmatrix
#define THREADS 256
#define MAX_TILES 24
#define STAGES 3
#define SBW (BM * HKP)                       // words per tile buffer (4608)
#define SMEM_BYTES (2 * STAGES * SBW * 4)    // As + Bs = 110592 bytes

// Scratch (device globals — allocation is forbidden)
__device__ int      g_pair_src[T_ * K_];
__device__ int      g_tile_e[MAX_TILES];
__device__ int      g_tile_start[MAX_TILES];
__device__ int      g_tile_cnt[MAX_TILES];
__device__ int      g_num_tiles;
__device__ uint32_t g_hs_h[(size_t)T_ * H_ / 2];             // 4 MB fp16x2
__device__ uint32_t g_wgu_h[(size_t)E_ * 2 * I_ * H_ / 2];   // 67 MB fp16x2
__device__ uint32_t g_dn_h[(size_t)E_ * H_ * I_ / 2];        // 33.5 MB fp16x2
__device__ uint32_t g_inter_h[(size_t)T_ * K_ * I_ / 2];     // 4 MB fp16x2

// ---------------------------------------------------------------- helpers
__device__ __forceinline__ uint32_t pack_h2(float lo, float hi) {
    uint32_t r; asm("cvt.rn.f16x2.f32 %0, %1, %2;" : "=r"(r) : "f"(hi), "f"(lo));
    return r;
}

__device__ __forceinline__ void mma_f16(float* c, const uint32_t* a, const uint32_t* b) {
    asm volatile(
        "mma.sync.aligned.m16n8k16.row.col.f32.f16.f16.f32 "
        "{%0,%1,%2,%3}, {%4,%5,%6,%7}, {%8,%9}, {%0,%1,%2,%3};"
        : "+f"(c[0]), "+f"(c[1]), "+f"(c[2]), "+f"(c[3])
        : "r"(a[0]), "r"(a[1]), "r"(a[2]), "r"(a[3]), "r"(b[0]), "r"(b[1]));
}

#define LDSM_X4(r0, r1, r2, r3, addr)                                       \
    asm volatile("ldmatrix.sync.aligned.m8n8.x4.shared.b16 {%0,%1,%2,%3}, [%4];" \
                 : "=r"(r0), "=r"(r1), "=r"(r2), "=r"(r3) : "r"(addr))

__device__ __forceinline__ void cp16(uint32_t dst, const void* src, int srcsize) {
    asm volatile("cp.async.cg.shared.global [%0], [%1], 16, %2;"
                 :: "r"(dst), "l"(src), "r"(srcsize));
}
#define CP_COMMIT()  asm volatile("cp.async.commit_group;")
#define CP_WAIT1()   asm volatile("cp.async.wait_group 1;")

__device__ __forceinline__ float silu(float x) {
    return x / (1.f + __expf(-x));
}

__device__ __forceinline__ float4 ldg4(const float* p) {
    return __ldg((const float4*)p);
}

// ---------------------------------------------------------------- fp32 -> fp16 convert
__global__ void convert_kernel(const float* __restrict__ hs,
                               const float* __restrict__ wgu,
                               const float* __restrict__ dn) {
    const size_t stride = (size_t)gridDim.x * blockDim.x;
    const size_t i0 = (size_t)blockIdx.x * blockDim.x + threadIdx.x;
    for (size_t q = i0; q < (size_t)T_ * H_ / 4; q += stride) {
        float4 v = ldg4(hs + 4 * q);
        *(uint2*)&g_hs_h[2 * q] = make_uint2(pack_h2(v.x, v.y), pack_h2(v.z, v.w));
    }
    for (size_t q = i0; q < (size_t)E_ * 2 * I_ * H_ / 4; q += stride) {
        float4 v = ldg4(wgu + 4 * q);
        *(uint2*)&g_wgu_h[2 * q] = make_uint2(pack_h2(v.x, v.y), pack_h2(v.z, v.w));
    }
    for (size_t q = i0; q < (size_t)E_ * H_ * I_ / 4; q += stride) {
        float4 v = ldg4(dn + 4 * q);
        *(uint2*)&g_dn_h[2 * q] = make_uint2(pack_h2(v.x, v.y), pack_h2(v.z, v.w));
    }
}

// ---------------------------------------------------------------- routing
__global__ void route_kernel(const int* __restrict__ sel) {
    __shared__ int cnt[E_], cur[E_];
    int tid = threadIdx.x;
    if (tid < E_) cnt[tid] = 0;
    __syncthreads();
    for (int i = tid; i < T_ * K_; i += blockDim.x) {
        int e = min(max(sel[i], 0), E_ - 1);
        atomicAdd(&cnt[e], 1);
    }
    __syncthreads();
    if (tid == 0) {
        int off = 0, nt = 0;
        for (int e = 0; e < E_; e++) {
            cur[e] = off;
            for (int m = 0; m < cnt[e] && nt < MAX_TILES; m += BM) {
                g_tile_e[nt] = e;
                g_tile_start[nt] = off + m;
                g_tile_cnt[nt] = min(BM, cnt[e] - m);
                nt++;
            }
            off += cnt[e];
        }
        g_num_tiles = nt;
    }
    __syncthreads();
    for (int i = tid; i < T_ * K_; i += blockDim.x) {
        int e = min(max(sel[i], 0), E_ - 1);
        int pos = atomicAdd(&cur[e], 1);
        if (pos < T_ * K_) g_pair_src[pos] = i;   // i = t*K + slot; output row == i
    }
}

// ---------------------------------------------------------------- GEMM1
// inter[pair, n] = silu(x.Wg^T[n]) * (x.Wu^T[n]); CTA: 128 pairs x 64 n-cols.
// C tile 128x128: cols 0..63 = gate(nblk*64..), cols 64..127 = up(same).
__global__ void __launch_bounds__(THREADS, 2)
gemm1_kernel() {
    const int tile = blockIdx.x;
    if (tile >= g_num_tiles) return;
    const int nblk = blockIdx.y;                 // 0..15  (I/64)
    const int e     = g_tile_e[tile];
    const int start = g_tile_start[tile];
    const int cnt   = g_tile_cnt[tile];
    const int tid = threadIdx.x, wid = tid >> 5, lane = tid & 31;
    const int wm = wid & 3, wn = wid >> 2;

    extern __shared__ uint32_t sm[];
    uint32_t* Asm = sm;                  // [STAGES][BM][HKP] fp16x2 words
    uint32_t* Bsm = sm + STAGES * SBW;
    __shared__ int s_tok[BM];

    if (tid < BM) {
        int v = (tid < cnt) ? g_pair_src[start + tid] : 0;
        s_tok[tid] = v / K_;
    }
    __syncthreads();

    const uint32_t* wbh = g_wgu_h + (size_t)e * (2 * I_) * (H_ / 2);

    // cp.async: chunk = 128 rows x 8 quads; idx = tid + j*256 -> row=idx>>3, q=idx&7
    uint32_t a_dst[4], b_dst[4];
    const uint32_t* a_src[4];
    const uint32_t* b_src[4];
    int a_sz[4];
#pragma unroll
    for (int j = 0; j < 4; j++) {
        int ia = tid + j * THREADS;
        int r = ia >> 3, q = ia & 7;
        a_dst[j] = (uint32_t)__cvta_generic_to_shared(&Asm[r * HKP + q * 4]);
        b_dst[j] = (uint32_t)__cvta_generic_to_shared(&Bsm[r * HKP + q * 4]);
        a_src[j] = g_hs_h + (size_t)s_tok[r] * (H_ / 2) + q * 4;
        int wr = (r < 64) ? (nblk * 64 + r) : (I_ + nblk * 64 + r - 64);
        b_src[j] = wbh + (size_t)wr * (H_ / 2) + q * 4;
        a_sz[j] = (r < cnt) ? 16 : 0;
    }

    // ldmatrix per-lane byte offsets within a tile buffer
    const uint32_t Asm_s = (uint32_t)__cvta_generic_to_shared(Asm);
    const uint32_t Bsm_s = (uint32_t)__cvta_generic_to_shared(Bsm);
    uint32_t a_lm[2];
#pragma unroll
    for (int mb = 0; mb < 2; mb++) {
        int row = wm * 32 + mb * 16 + (lane & 15);
        a_lm[mb] = (uint32_t)((row * HKP + (lane >> 4) * 4) * 4);
    }
    uint32_t b_lm[4];
#pragma unroll
    for (int p = 0; p < 4; p++) {
        int rowbase = (p < 2) ? (wn * 32 + p * 16) : (64 + wn * 32 + (p - 2) * 16);
        int row = rowbase + (lane & 7) + ((lane >> 4) << 3);
        b_lm[p] = (uint32_t)((row * HKP + ((lane >> 3) & 1) * 4) * 4);
    }

    float acc[2][8][4];
#pragma unroll
    for (int mb = 0; mb < 2; mb++)
#pragma unroll
        for (int nb = 0; nb < 8; nb++)
#pragma unroll
            for (int i = 0; i < 4; i++) acc[mb][nb][i] = 0.f;

    const int NK = H_ / KC;          // 32 chunks, each 32 words/row
#pragma unroll
    for (int s = 0; s < STAGES - 1; s++) {
        const uint32_t boff = (uint32_t)s * SBW * 4;
#pragma unroll
        for (int j = 0; j < 4; j++) {
            cp16(a_dst[j] + boff, a_src[j] + s * 32, a_sz[j]);
            cp16(b_dst[j] + boff, b_src[j] + s * 32, 16);
        }
        CP_COMMIT();
    }

#pragma unroll 1
    for (int kk = 0; kk < NK; kk++) {
        CP_WAIT1();
        __syncthreads();
        const uint32_t ab = Asm_s + (uint32_t)(kk % STAGES) * SBW * 4;
        const uint32_t bb = Bsm_s + (uint32_t)(kk % STAGES) * SBW * 4;
#pragma unroll
        for (int s2 = 0; s2 < 4; s2++) {                  // four k16 slabs
            const uint32_t kb = (uint32_t)(s2 * 8 * 4);   // slab byte offset
            uint32_t af[2][4];
            LDSM_X4(af[0][0], af[0][1], af[0][2], af[0][3], ab + a_lm[0] + kb);
            LDSM_X4(af[1][0], af[1][1], af[1][2], af[1][3], ab + a_lm[1] + kb);
            uint32_t bf[8][2];
#pragma unroll
            for (int p = 0; p < 4; p++)
                LDSM_X4(bf[2 * p][0], bf[2 * p][1], bf[2 * p + 1][0], bf[2 * p + 1][1],
                        bb + b_lm[p] + kb);
#pragma unroll
            for (int mb = 0; mb < 2; mb++)
#pragma unroll
                for (int nb = 0; nb < 8; nb++)
                    mma_f16(acc[mb][nb], af[mb], bf[nb]);
        }
        const int nc = kk + STAGES - 1;
        if (nc < NK) {
            const uint32_t boff = (uint32_t)(nc % STAGES) * SBW * 4;
#pragma unroll
            for (int j = 0; j < 4; j++) {
                cp16(a_dst[j] + boff, a_src[j] + nc * 32, a_sz[j]);
                cp16(b_dst[j] + boff, b_src[j] + nc * 32, 16);
            }
        }
        CP_COMMIT();
    }

    // epilogue: silu(gate)*up -> g_inter_h (fp16x2 words; c0/c1 = cols 2t,2t+1)
    const int g = lane >> 2, t = lane & 3;
#pragma unroll
    for (int mb = 0; mb < 2; mb++) {
        int r0 = wm * 32 + mb * 16 + g;
#pragma unroll
        for (int nb = 0; nb < 4; nb++) {
            int colw = (nblk * 64 + wn * 32 + nb * 8) / 2 + t;
            const float* cg = acc[mb][nb];
            const float* cu = acc[mb][nb + 4];
            if (r0 < cnt)
                g_inter_h[(size_t)(start + r0) * (I_ / 2) + colw] =
                    pack_h2(silu(cg[0]) * cu[0], silu(cg[1]) * cu[1]);
            if (r0 + 8 < cnt)
                g_inter_h[(size_t)(start + r0 + 8) * (I_ / 2) + colw] =
                    pack_h2(silu(cg[2]) * cu[2], silu(cg[3]) * cu[3]);
        }
    }
}

// ---------------------------------------------------------------- GEMM2
// out[src(pair), h] = inter[pair, :] . down[e, h, :]; CTA: 128 pairs x 128 h.
__global__ void __launch_bounds__(THREADS, 2)
gemm2_kernel(float* __restrict__ out) {
    const int tile = blockIdx.x;
    if (tile >= g_num_tiles) return;
    const int nblk = blockIdx.y;                 // 0..15  (H/128)
    const int e     = g_tile_e[tile];
    const int start = g_tile_start[tile];
    const int cnt   = g_tile_cnt[tile];
    const int tid = threadIdx.x, wid = tid >> 5, lane = tid & 31;
    const int wm = wid & 3, wn = wid >> 2;

    extern __shared__ uint32_t sm[];
    uint32_t* Asm = sm;
    uint32_t* Bsm = sm + STAGES * SBW;
    __shared__ int s_src[BM];

    if (tid < BM)
        s_src[tid] = (tid < cnt) ? g_pair_src[start + tid] : 0;
    __syncthreads();

    const uint32_t* wbh = g_dn_h + ((size_t)e * H_ + (size_t)nblk * 128) * (I_ / 2);

    uint32_t a_dst[4], b_dst[4];
    const uint32_t* a_src[4];
    const uint32_t* b_src[4];
    int a_sz[4];
#pragma unroll
    for (int j = 0; j < 4; j++) {
        int ia = tid + j * THREADS;
        int r = ia >> 3, q = ia & 7;
        a_dst[j] = (uint32_t)__cvta_generic_to_shared(&Asm[r * HKP + q * 4]);
        b_dst[j] = (uint32_t)__cvta_generic_to_shared(&Bsm[r * HKP + q * 4]);
        a_src[j] = g_inter_h + (size_t)(start + ((r < cnt) ? r : 0)) * (I_ / 2) + q * 4;
        b_src[j] = wbh + (size_t)r * (I_ / 2) + q * 4;
        a_sz[j] = (r < cnt) ? 16 : 0;
    }

    const uint32_t Asm_s = (uint32_t)__cvta_generic_to_shared(Asm);
    const uint32_t Bsm_s = (uint32_t)__cvta_generic_to_shared(Bsm);
    uint32_t a_lm[2];
#pragma unroll
    for (int mb = 0; mb < 2; mb++) {
        int row = wm * 32 + mb * 16 + (lane & 15);
        a_lm[mb] = (uint32_t)((row * HKP + (lane >> 4) * 4) * 4);
    }
    uint32_t b_lm[4];
#pragma unroll
    for (int p = 0; p < 4; p++) {
        int row = wn * 64 + p * 16 + (lane & 7) + ((lane >> 4) << 3);
        b_lm[p] = (uint32_t)((row * HKP + ((lane >> 3) & 1) * 4) * 4);
    }

    float acc[2][8][4];
#pragma unroll
    for (int mb = 0; mb < 2; mb++)
#pragma unroll
        for (int nb = 0; nb < 8; nb++)
#pragma unroll
            for (int i = 0; i < 4; i++) acc[mb][nb][i] = 0.f;

    const int NK = I_ / KC;          // 16 chunks
#pragma unroll
    for (int s = 0; s < STAGES - 1; s++) {
        const uint32_t boff = (uint32_t)s * SBW * 4;
#pragma unroll
        for (int j = 0; j < 4; j++) {
            cp16(a_dst[j] + boff, a_src[j] + s * 32, a_sz[j]);
            cp16(b_dst[j] + boff, b_src[j] + s * 32, 16);
        }
        CP_COMMIT();
    }

#pragma unroll 1
    for (int kk = 0; kk < NK; kk++) {
        CP_WAIT1();
        __syncthreads();
        const uint32_t ab = Asm_s + (uint32_t)(kk % STAGES) * SBW * 4;
        const uint32_t bb = Bsm_s + (uint32_t)(kk % STAGES) * SBW * 4;
#pragma unroll
        for (int s2 = 0; s2 < 4; s2++) {
            const uint32_t kb = (uint32_t)(s2 * 8 * 4);
            uint32_t af[2][4];
            LDSM_X4(af[0][0], af[0][1], af[0][2], af[0][3], ab + a_lm[0] + kb);
            LDSM_X4(af[1][0], af[1][1], af[1][2], af[1][3], ab + a_lm[1] + kb);
            uint32_t bf[8][2];
#pragma unroll
            for (int p = 0; p < 4; p++)
                LDSM_X4(bf[2 * p][0], bf[2 * p][1], bf[2 * p + 1][0], bf[2 * p + 1][1],
                        bb + b_lm[p] + kb);
#pragma unroll
            for (int mb = 0; mb < 2; mb++)
#pragma unroll
                for (int nb = 0; nb < 8; nb++)
                    mma_f16(acc[mb][nb], af[mb], bf[nb]);
        }
        const int nc = kk + STAGES - 1;
        if (nc < NK) {
            const uint32_t boff = (uint32_t)(nc % STAGES) * SBW * 4;
#pragma unroll
            for (int j = 0; j < 4; j++) {
                cp16(a_dst[j] + boff, a_src[j] + nc * 32, a_sz[j]);
                cp16(b_dst[j] + boff, b_src[j] + nc * 32, 16);
            }
        }
        CP_COMMIT();
    }

    // epilogue: scatter rows to out[src] (fp32)
    const int g = lane >> 2, t = lane & 3;
#pragma unroll
    for (int mb = 0; mb < 2; mb++) {
        int r0 = wm * 32 + mb * 16 + g;
        int src0 = s_src[r0 & (BM - 1)];
        int src1 = s_src[(r0 + 8) & (BM - 1)];
#pragma unroll
        for (int nb = 0; nb < 8; nb++) {
            int col = nblk * 128 + wn * 64 + nb * 8 + 2 * t;
            const float* c = acc[mb][nb];
            if (r0 < cnt)
                *(float2*)(out + (size_t)src0 * H_ + col) = make_float2(c[0], c[1]);
            if (r0 + 8 < cnt)
                *(float2*)(out + (size_t)src1 * H_ + col) = make_float2(c[2], c[3]);
        }
    }
}

// ---------------------------------------------------------------- launch
extern "C" void kernel_launch(void* const* d_in, const int* in_sizes, int n_in,
                              void* d_out, int out_size) {
    // Identify inputs by element count (robust to metadata ordering)
    const float* hs  = nullptr;
    const int*   sel = nullptr;
    const float* wgu = nullptr;
    const float* dn  = nullptr;
    for (int i = 0; i < n_in; i++) {
        long long n = in_sizes[i];
        if (n == (long long)T_ * H_)               hs  = (const float*)d_in[i];
        else if (n == (long long)T_ * K_)          sel = (const int*)d_in[i];
        else if (n == (long long)E_ * 2 * I_ * H_) wgu = (const float*)d_in[i];
        else if (n == (long long)E_ * H_ * I_)     dn  = (const float*)d_in[i];
    }
    float* out = (float*)d_out;
    if (!hs || !sel || !wgu || !dn) return;

    cudaFuncSetAttribute(gemm1_kernel, cudaFuncAttributeMaxDynamicSharedMemorySize, SMEM_BYTES);
    cudaFuncSetAttribute(gemm2_kernel, cudaFuncAttributeMaxDynamicSharedMemorySize, SMEM_BYTES);

    convert_kernel<<<2048, 256>>>(hs, wgu, dn);
    route_kernel<<<1, 256>>>(sel);
    gemm1_kernel<<<dim3(MAX_TILES, I_ / 64), THREADS, SMEM_BYTES>>>();
    gemm2_kernel<<<dim3(MAX_TILES, H_ / 128), THREADS, SMEM_BYTES>>>(out);
}